// round 14
// baseline (speedup 1.0000x reference)
#include <cuda_runtime.h>
#include <math.h>

// ---------------------------------------------------------------------------
// NCC3D: z[8,1,8,8,8], x[8,1,128,128,128] -> out[8,1,121,121,121]
//   k_template : zero-mean template + L2 norm
//   k_stats    : FUSED W+H+D window stats -> g_dinv directly. One block per
//                (ho-chunk of 7, b); marches d with double-buffered x slice,
//                register-prefetched LDG, smem H-sum ring, register rolling
//                D sums. No g_t1/g_t2 intermediates.
//   k_cross    : direct correlation, f32x2 packed FMA (R11 measured version)
// ---------------------------------------------------------------------------

#define NB 8
typedef unsigned long long ull;

__device__ float g_zc[NB * 512];
__device__ float g_zn[NB];
__device__ float g_dinv[(size_t)NB * 121 * 121 * 121];

// ---------------- packed f32x2 helpers ----------------
__device__ __forceinline__ void fma2(ull& a, ull x, ull z) {
    asm("fma.rn.f32x2 %0, %1, %2, %0;" : "+l"(a) : "l"(x), "l"(z));
}
__device__ __forceinline__ float2 u2f(ull u) {
    float2 f;
    asm("mov.b64 {%0, %1}, %2;" : "=f"(f.x), "=f"(f.y) : "l"(u));
    return f;
}
__device__ __forceinline__ ull dupf(float f) {
    ull r;
    asm("mov.b64 %0, {%1, %1};" : "=l"(r) : "f"(f));
    return r;
}

// ---------------- template stats ----------------
__global__ void ncc_k_template(const float* __restrict__ z) {
    __shared__ float red[512];
    int b = blockIdx.x, t = threadIdx.x;
    float v = z[b * 512 + t];
    red[t] = v;
    __syncthreads();
    for (int s = 256; s > 0; s >>= 1) {
        if (t < s) red[t] += red[t + s];
        __syncthreads();
    }
    float mean = red[0] * (1.0f / 512.0f);
    __syncthreads();
    float c = v - mean;
    g_zc[b * 512 + t] = c;
    red[t] = c * c;
    __syncthreads();
    for (int s = 256; s > 0; s >>= 1) {
        if (t < s) red[t] += red[t + s];
        __syncthreads();
    }
    if (t == 0) g_zn[b] = sqrtf(red[0]);
}

// ---------------- fused W+H+D stats -> g_dinv -------------------------------
// Block = (chunk, b). chunk covers output ho0..ho0+6 (ho0 = 7*chunk, 18 chunks).
// Needs h rows ho0..ho0+13 (clamped). Marches d = 0..127:
//   stage[d&1]: x slice [14][132] (cols 128..131 zeroed once)
//   W pass    : ws1/ws2[14][124] per-output 8-tap sums
//   H pass    : per-w-column rolling (tid<124): Hsum(ho) for ho_l 0..6,
//               pushed to ring hs[8][7][124]; rolling D sums rs1/rs2[7] in
//               registers (+= new - ring evictee); dinv emitted for d-7.
// Prefetch: next d's x LDG'd into registers at iter top, STS'd after H.
#define ST_CH 7
#define ST_ROWS 14
#define ST_XP 132
#define ST_WP 124
#define ST_XBUF (ST_ROWS * ST_XP)             // 1848 floats
#define ST_RING (8 * ST_CH * ST_WP)           // 6944 floats
#define ST_SMEM ((2 * ST_XBUF + 2 * ST_ROWS * ST_WP + 2 * ST_RING) * 4)  // 84224 B

__global__ void __launch_bounds__(256, 1) ncc_k_stats(const float* __restrict__ x) {
    extern __shared__ float sm[];
    float* xst = sm;                          // [2][14][132]
    float* ws1 = sm + 2 * ST_XBUF;            // [14][124]
    float* ws2 = ws1 + ST_ROWS * ST_WP;
    float* hs1 = ws2 + ST_ROWS * ST_WP;       // [8][7][124]
    float* hs2 = hs1 + ST_RING;

    int chunk = blockIdx.x, b = blockIdx.y;
    int ho0 = chunk * ST_CH;
    int tid = threadIdx.x;
    const float* xb = x + (size_t)b * 2097152;
    float zn = g_zn[b];

    // zero ring + x-stage pad columns (128..131) of both buffers
    for (int i = tid; i < ST_RING; i += 256) { hs1[i] = 0.f; hs2[i] = 0.f; }
    for (int i = tid; i < 2 * ST_ROWS; i += 256)
        *(float4*)(xst + i * ST_XP + 128) = make_float4(0.f, 0.f, 0.f, 0.f);

    float rs1[ST_CH], rs2[ST_CH];
#pragma unroll
    for (int k = 0; k < ST_CH; k++) { rs1[k] = 0.f; rs2[k] = 0.f; }

    // stage d=0 into buffer 0
    for (int i = tid; i < ST_ROWS * 32; i += 256) {
        int r = i >> 5, g = i & 31;
        int gh = min(ho0 + r, 127);
        float4 v = *(const float4*)(xb + gh * 128 + g * 4);
        *(float4*)(xst + r * ST_XP + g * 4) = v;
    }
    __syncthreads();

    // fixed prefetch task assignment (448 tasks, <=2 per thread)
    bool has1 = (tid < ST_ROWS * 32 - 256);   // tid < 192
    int r0 = tid >> 5, g0 = tid & 31;
    int t1 = tid + 256;
    int r1 = t1 >> 5, g1 = t1 & 31;
    int gh0 = min(ho0 + r0, 127), gh1 = min(ho0 + r1, 127);

    for (int d = 0; d < 128; d++) {
        const float* xbuf = xst + (d & 1) * ST_XBUF;
        float* nbuf = xst + ((d + 1) & 1) * ST_XBUF;

        float4 pf0, pf1;
        if (d < 127) {
            const float* xn = xb + (size_t)(d + 1) * 16384;
            pf0 = *(const float4*)(xn + gh0 * 128 + g0 * 4);
            if (has1) pf1 = *(const float4*)(xn + gh1 * 128 + g1 * 4);
        }

        // ---- W pass: 14 rows x 124 outputs ----
        for (int i = tid; i < ST_ROWS * 128; i += 256) {
            int r = i >> 7, w = i & 127;
            if (w < ST_WP) {
                const float* p = xbuf + r * ST_XP + w;
                float a = 0.f, c = 0.f;
#pragma unroll
                for (int j = 0; j < 8; j++) { float v = p[j]; a += v; c += v * v; }
                ws1[r * ST_WP + w] = a;
                ws2[r * ST_WP + w] = c;
            }
        }
        __syncthreads();

        // ---- H rolling + ring + rolling D + dinv (one thread per w) ----
        if (tid < ST_WP) {
            int w = tid;
            float a1 = 0.f, a2 = 0.f, w1[8], w2[8];
#pragma unroll
            for (int k = 0; k < 8; k++) {
                w1[k] = ws1[k * ST_WP + w]; a1 += w1[k];
                w2[k] = ws2[k * ST_WP + w]; a2 += w2[k];
            }
            float* ring1 = hs1 + (d & 7) * (ST_CH * ST_WP) + w;
            float* ring2 = hs2 + (d & 7) * (ST_CH * ST_WP) + w;
#pragma unroll
            for (int ho = 0; ho < ST_CH; ho++) {
                float o1 = ring1[ho * ST_WP], o2 = ring2[ho * ST_WP];
                rs1[ho] += a1 - o1; ring1[ho * ST_WP] = a1;
                rs2[ho] += a2 - o2; ring2[ho * ST_WP] = a2;
                if (d >= 7 && w < 121 && ho0 + ho <= 120) {
                    float s1v = rs1[ho], s2v = rs2[ho];
                    float var = fmaxf(s2v - s1v * s1v * (1.0f / 512.0f), 0.f);
                    g_dinv[(((size_t)(b * 121 + (d - 7))) * 121 + (ho0 + ho)) * 121 + w] =
                        1.0f / (sqrtf(var + 1e-12f) * zn + 1e-5f);
                }
                if (ho < ST_CH - 1) {
                    float n1 = ws1[(ho + 8) * ST_WP + w];
                    float n2 = ws2[(ho + 8) * ST_WP + w];
                    a1 += n1 - w1[ho];
                    a2 += n2 - w2[ho];
                }
            }
        }

        // ---- store prefetched next slice ----
        if (d < 127) {
            *(float4*)(nbuf + r0 * ST_XP + g0 * 4) = pf0;
            if (has1) *(float4*)(nbuf + r1 * ST_XP + g1 * 4) = pf1;
        }
        __syncthreads();
    }
}

// ---------------- cross-correlation (R11 measured version) ------------------
// Block 256 threads = 8 warps, 2 blocks/SM. Output tile: 4(d) x 8(h) x 128(w).
// Thread: od = c>>2 (0..3), oh0 = (c&3)*2 (phases 0/1), wt = tid&15, 8 w each.
// Accumulators per phase: even bank A[4] (out pairs 2p,2p+1), odd bank B[5]
// (out pairs 2i-1,2i). Tile row r+1 prefetched before phase0 FMAs; phase1 of
// iter r uses tile row r+1 + z row r. z stored PLAIN in smem; z chunks
// double-buffered. Tile rows swizzled by 16B granule: phys = g ^ (g>>3),
// row stride 152 floats (38 granules, == 6 mod 8) -> conflict-free LDS.128.
#define CTD 11
#define CTHH 15
#define RST 152
#define TILE_F (CTD * CTHH * RST)            // 25,080 floats
#define CR_SMEM ((TILE_F + 512) * 4)         // + 512 plain z floats

__device__ __forceinline__ void cr_loadrow(ull* pe, const float* rp,
                                           const int* off) {
#pragma unroll
    for (int q = 0; q < 4; q++) {
        ulonglong2 v = *(const ulonglong2*)(rp + off[q]);
        pe[2 * q] = v.x;
        pe[2 * q + 1] = v.y;
    }
}
__device__ __forceinline__ void cr_loadz(float* zc, const float* zk) {
#pragma unroll
    for (int q = 0; q < 4; q++) {
        float4 v = *(const float4*)(zk + (q << 2));
        zc[4 * q] = v.x; zc[4 * q + 1] = v.y;
        zc[4 * q + 2] = v.z; zc[4 * q + 3] = v.w;
    }
}
__device__ __forceinline__ void cr_fma(ull* A, ull* B, const ull* pe,
                                       const ull* zr) {
#pragma unroll
    for (int m = 0; m < 4; m++) {
        ull ze = zr[2 * m];
#pragma unroll
        for (int p = 0; p < 4; p++) fma2(A[p], pe[p + m], ze);
    }
#pragma unroll
    for (int m = 0; m < 4; m++) {
        ull zo = zr[2 * m + 1];
#pragma unroll
        for (int i = 0; i < 5; i++) fma2(B[i], pe[i + m], zo);
    }
}

__global__ void __launch_bounds__(256, 2) ncc_k_cross(const float* __restrict__ x,
                                                      float* __restrict__ out) {
    extern __shared__ float sm[];
    float* tile = sm;
    float* zs = sm + TILE_F;                 // plain z floats [512]

    int b = blockIdx.z;
    int d0 = blockIdx.x * 4, h0 = blockIdx.y * 8;
    int tid = threadIdx.x;

    // ---- vectorized prologue: 165 rows x 32 data granules, LDG.128/STS.128
    const float* xb = x + (size_t)b * 2097152;
    for (int i = tid; i < 165 * 32; i += 256) {
        int row = i >> 5;
        int g = i & 31;
        int phys = g ^ (g >> 3);
        int dd = row / CTHH, hh = row - dd * CTHH;
        int gd = min(d0 + dd, 127), gh = min(h0 + hh, 127);
        float4 v = *(const float4*)(xb + ((size_t)(gd * 128 + gh) << 7) + (g << 2));
        *(float4*)(tile + row * RST + (phys << 2)) = v;
    }
    // zero pad granules: logical 32,33 -> phys 36,37
    for (int i = tid; i < 165 * 2; i += 256) {
        int row = i >> 1;
        int phys = 36 + (i & 1);
        *(float4*)(tile + row * RST + (phys << 2)) = make_float4(0.f, 0.f, 0.f, 0.f);
    }
    for (int t = tid; t < 512; t += 256) zs[t] = g_zc[b * 512 + t];
    __syncthreads();

    int wt = tid & 15, c = tid >> 4;
    int od = c >> 2, oh0 = (c & 3) * 2;
    int wb = wt * 8;

    int off[4];
#pragma unroll
    for (int q = 0; q < 4; q++) {
        int g = 2 * wt + q;
        off[q] = (g ^ (g >> 3)) << 2;        // swizzled float offset
    }

    ull A0[4], B0[5], A1[4], B1[5];
#pragma unroll
    for (int p = 0; p < 4; p++) { A0[p] = 0ull; A1[p] = 0ull; }
#pragma unroll
    for (int i = 0; i < 5; i++) { B0[i] = 0ull; B1[i] = 0ull; }

#pragma unroll 1
    for (int kd = 0; kd < 8; kd++) {
        const float* bp = tile + (od + kd) * (CTHH * RST) + oh0 * RST;
        const float* zk = zs + (kd << 6);    // 64 plain z floats for this kd

        ull peb[2][8];
        cr_loadrow(peb[0], bp, off);

        float zcb[2][16];                    // double-buffered z chunks
        cr_loadz(zcb[0], zk);

#pragma unroll
        for (int rh = 0; rh < 4; rh++) {
            if (rh < 3) cr_loadz(zcb[(rh + 1) & 1], zk + ((rh + 1) << 4));
            const float* zc = zcb[rh & 1];
#pragma unroll
            for (int rr = 0; rr < 2; rr++) {
                int r = rh * 2 + rr;
                ull zd[8];
#pragma unroll
                for (int j = 0; j < 8; j++) zd[j] = dupf(zc[rr * 8 + j]);
                cr_loadrow(peb[(r + 1) & 1], bp + (r + 1) * RST, off);
                // phase0: output row oh0,   tile row r,   z row r
                cr_fma(A0, B0, peb[r & 1], zd);
                // phase1: output row oh0+1, tile row r+1, z row r
                cr_fma(A1, B1, peb[(r + 1) & 1], zd);
            }
        }
    }

    int d = d0 + od;
    if (d >= 121) return;
    size_t dbase_o = ((size_t)(b * 121 + d)) * 121;

    {
        int h = h0 + oh0;
        if (h < 121) {
            float res[8];
#pragma unroll
            for (int p = 0; p < 4; p++) {
                float2 a = u2f(A0[p]);
                float2 bl = u2f(B0[p]);
                float2 br = u2f(B0[p + 1]);
                res[2 * p] = a.x + bl.y;
                res[2 * p + 1] = a.y + br.x;
            }
            size_t base = (dbase_o + h) * 121;
#pragma unroll
            for (int j = 0; j < 8; j++) {
                int w = wb + j;
                if (w < 121) out[base + w] = res[j] * __ldg(&g_dinv[base + w]);
            }
        }
    }
    {
        int h = h0 + oh0 + 1;
        if (h < 121) {
            float res[8];
#pragma unroll
            for (int p = 0; p < 4; p++) {
                float2 a = u2f(A1[p]);
                float2 bl = u2f(B1[p]);
                float2 br = u2f(B1[p + 1]);
                res[2 * p] = a.x + bl.y;
                res[2 * p + 1] = a.y + br.x;
            }
            size_t base = (dbase_o + h) * 121;
#pragma unroll
            for (int j = 0; j < 8; j++) {
                int w = wb + j;
                if (w < 121) out[base + w] = res[j] * __ldg(&g_dinv[base + w]);
            }
        }
    }
}

// ---------------------------------------------------------------------------
extern "C" void kernel_launch(void* const* d_in, const int* in_sizes, int n_in,
                              void* d_out, int out_size) {
    (void)n_in;
    (void)out_size;
    const float* z = (const float*)d_in[0];
    const float* x = (const float*)d_in[1];
    if (in_sizes[0] != NB * 512) {
        z = (const float*)d_in[1];
        x = (const float*)d_in[0];
    }
    float* out = (float*)d_out;

    cudaFuncSetAttribute(ncc_k_stats,
                         cudaFuncAttributeMaxDynamicSharedMemorySize, ST_SMEM);
    cudaFuncSetAttribute(ncc_k_cross,
                         cudaFuncAttributeMaxDynamicSharedMemorySize, CR_SMEM);

    ncc_k_template<<<NB, 512>>>(z);
    ncc_k_stats<<<dim3(18, NB), 256, ST_SMEM>>>(x);
    ncc_k_cross<<<dim3(31, 16, NB), 256, CR_SMEM>>>(x, out);
}

// round 15
// speedup vs baseline: 1.1677x; 1.1677x over previous
#include <cuda_runtime.h>
#include <math.h>

// ---------------------------------------------------------------------------
// NCC3D: z[8,1,8,8,8], x[8,1,128,128,128] -> out[8,1,121,121,121]
//   k_template : zero-mean template + L2 norm (+ reciprocal norm)
//   k_whsum2   : W+H window sums, half-slice blocks (70KB smem, 3 blocks/SM),
//                rolling-register W pass, rolling H pass per (w, ho-strip)
//   k_dsum2    : rolling D window sums + denominator via single rsqrt MUFU
//   k_cross    : direct correlation, f32x2 packed FMA (R11 measured version)
// ---------------------------------------------------------------------------

#define NB 8
typedef unsigned long long ull;

__device__ float g_zc[NB * 512];
__device__ float g_rzn[NB];
__device__ float g_t1[(size_t)NB * 128 * 121 * 121];
__device__ float g_t2[(size_t)NB * 128 * 121 * 121];
__device__ float g_dinv[(size_t)NB * 121 * 121 * 121];

// ---------------- packed f32x2 helpers ----------------
__device__ __forceinline__ void fma2(ull& a, ull x, ull z) {
    asm("fma.rn.f32x2 %0, %1, %2, %0;" : "+l"(a) : "l"(x), "l"(z));
}
__device__ __forceinline__ float2 u2f(ull u) {
    float2 f;
    asm("mov.b64 {%0, %1}, %2;" : "=f"(f.x), "=f"(f.y) : "l"(u));
    return f;
}
__device__ __forceinline__ ull dupf(float f) {
    ull r;
    asm("mov.b64 %0, {%1, %1};" : "=l"(r) : "f"(f));
    return r;
}

// ---------------- template stats ----------------
__global__ void ncc_k_template(const float* __restrict__ z) {
    __shared__ float red[512];
    int b = blockIdx.x, t = threadIdx.x;
    float v = z[b * 512 + t];
    red[t] = v;
    __syncthreads();
    for (int s = 256; s > 0; s >>= 1) {
        if (t < s) red[t] += red[t + s];
        __syncthreads();
    }
    float mean = red[0] * (1.0f / 512.0f);
    __syncthreads();
    float c = v - mean;
    g_zc[b * 512 + t] = c;
    red[t] = c * c;
    __syncthreads();
    for (int s = 256; s > 0; s >>= 1) {
        if (t < s) red[t] += red[t + s];
        __syncthreads();
    }
    if (t == 0) g_rzn[b] = rsqrtf(red[0]);   // 1 / ||zc||
}

// ---------------- W + H window sums, half-slice (3 blocks/SM) ---------------
#define SS_PITCH 124
#define WH2_SMEM (2 * 71 * SS_PITCH * 4)

template <int NLD, int NOUT>
__device__ __forceinline__ void wpass_seg(const float* __restrict__ xrow,
                                          float* o1, float* o2) {
    float f[NLD * 4];
#pragma unroll
    for (int k = 0; k < NLD; k++) {
        float4 v = *(const float4*)(xrow + 4 * k);
        f[4 * k] = v.x; f[4 * k + 1] = v.y;
        f[4 * k + 2] = v.z; f[4 * k + 3] = v.w;
    }
    float a = 0.f, c = 0.f;
#pragma unroll
    for (int j = 0; j < 8; j++) { a += f[j]; c += f[j] * f[j]; }
    o1[0] = a; o2[0] = c;
#pragma unroll
    for (int j = 1; j < NOUT; j++) {
        float nv = f[j + 7], ov = f[j - 1];
        a += nv - ov;
        c += nv * nv - ov * ov;
        o1[j] = a; o2[j] = c;
    }
}

__global__ void __launch_bounds__(256, 3) ncc_k_whsum2(const float* __restrict__ x) {
    extern __shared__ float sm[];
    float* ss1 = sm;
    float* ss2 = sm + 71 * SS_PITCH;

    int half = blockIdx.x;
    int bd = blockIdx.y;
    int tid = threadIdx.x;
    int row0 = half * 64;
    int nrows = half ? 64 : 71;
    int nho = half ? 57 : 64;
    const float* xs = x + (size_t)bd * 16384;

    for (int t = tid; t < nrows * 4; t += 256) {
        int r = t >> 2, seg = t & 3;
        const float* xrow = xs + (row0 + r) * 128 + seg * 32;
        float* o1 = ss1 + r * SS_PITCH + seg * 32;
        float* o2 = ss2 + r * SS_PITCH + seg * 32;
        if (seg < 3) wpass_seg<10, 32>(xrow, o1, o2);
        else         wpass_seg<8, 25>(xrow, o1, o2);
    }
    __syncthreads();

    // H pass: rolling window. Thread = (w, strip): w = tid&127, 2 ho-strips.
    {
        int w = tid & 127, s = tid >> 7;
        int n0 = (nho + 1) >> 1;
        int hoS = s ? n0 : 0;
        int hoE = s ? nho : n0;
        if (w < 121) {
            float a = 0.f, c = 0.f;
#pragma unroll
            for (int k = 0; k < 8; k++) {
                a += ss1[(hoS + k) * SS_PITCH + w];
                c += ss2[(hoS + k) * SS_PITCH + w];
            }
            size_t o = ((size_t)bd * 121 + row0 + hoS) * 121 + w;
            for (int ho = hoS; ho < hoE; ho++) {
                g_t1[o] = a;
                g_t2[o] = c;
                o += 121;
                if (ho + 1 < hoE) {
                    a += ss1[(ho + 8) * SS_PITCH + w] - ss1[ho * SS_PITCH + w];
                    c += ss2[(ho + 8) * SS_PITCH + w] - ss2[ho * SS_PITCH + w];
                }
            }
        }
    }
}

// ---------------- rolling D sums + denominator inverse (1 MUFU) -------------
__global__ void __launch_bounds__(256) ncc_k_dsum2() {
    int p = blockIdx.x * 256 + threadIdx.x;
    if (p >= 14641) return;
    int h = p / 121, w = p - h * 121;
    int b = blockIdx.z;
    const int dst[5] = {0, 31, 61, 91, 121};
    int d0 = dst[blockIdx.y], d1 = dst[blockIdx.y + 1];
    size_t tbase = (((size_t)(b * 128)) * 121 + h) * 121 + w;
    float r1[8], r2[8], s1 = 0.f, s2 = 0.f;
#pragma unroll
    for (int k = 0; k < 8; k++) {
        float a = g_t1[tbase + (size_t)(d0 + k) * 14641];
        float c = g_t2[tbase + (size_t)(d0 + k) * 14641];
        r1[k] = a;
        r2[k] = c;
        s1 += a;
        s2 += c;
    }
    float rzn = g_rzn[b];
    size_t obase = (((size_t)(b * 121)) * 121 + h) * 121 + w;
    for (int dd = d0; dd < d1; dd += 8) {
#pragma unroll
        for (int j = 0; j < 8; j++) {
            int d = dd + j;
            if (d < d1) {
                float var = fmaxf(s2 - s1 * s1 * (1.0f / 512.0f), 0.0f);
                // 1/(sqrt(var)*zn) ; the +1e-5 term is rel ~2e-8 here
                g_dinv[obase + (size_t)d * 14641] =
                    rsqrtf(var + 1e-12f) * rzn;
                if (d + 1 < d1) {
                    float n1 = g_t1[tbase + (size_t)(d + 8) * 14641];
                    float n2 = g_t2[tbase + (size_t)(d + 8) * 14641];
                    s1 += n1 - r1[j];
                    r1[j] = n1;
                    s2 += n2 - r2[j];
                    r2[j] = n2;
                }
            }
        }
    }
}

// ---------------- cross-correlation (R11 measured version) ------------------
// Block 256 threads = 8 warps, 2 blocks/SM. Output tile: 4(d) x 8(h) x 128(w).
// Thread: od = c>>2 (0..3), oh0 = (c&3)*2 (phases 0/1), wt = tid&15, 8 w each.
// Accumulators per phase: even bank A[4] (out pairs 2p,2p+1), odd bank B[5]
// (out pairs 2i-1,2i). Tile row r+1 prefetched before phase0 FMAs; phase1 of
// iter r uses tile row r+1 + z row r. z stored PLAIN in smem; z chunks
// double-buffered. Tile rows swizzled by 16B granule: phys = g ^ (g>>3),
// row stride 152 floats (38 granules, == 6 mod 8) -> conflict-free LDS.128.
#define CTD 11
#define CTHH 15
#define RST 152
#define TILE_F (CTD * CTHH * RST)            // 25,080 floats
#define CR_SMEM ((TILE_F + 512) * 4)         // + 512 plain z floats

__device__ __forceinline__ void cr_loadrow(ull* pe, const float* rp,
                                           const int* off) {
#pragma unroll
    for (int q = 0; q < 4; q++) {
        ulonglong2 v = *(const ulonglong2*)(rp + off[q]);
        pe[2 * q] = v.x;
        pe[2 * q + 1] = v.y;
    }
}
__device__ __forceinline__ void cr_loadz(float* zc, const float* zk) {
#pragma unroll
    for (int q = 0; q < 4; q++) {
        float4 v = *(const float4*)(zk + (q << 2));
        zc[4 * q] = v.x; zc[4 * q + 1] = v.y;
        zc[4 * q + 2] = v.z; zc[4 * q + 3] = v.w;
    }
}
__device__ __forceinline__ void cr_fma(ull* A, ull* B, const ull* pe,
                                       const ull* zr) {
#pragma unroll
    for (int m = 0; m < 4; m++) {
        ull ze = zr[2 * m];
#pragma unroll
        for (int p = 0; p < 4; p++) fma2(A[p], pe[p + m], ze);
    }
#pragma unroll
    for (int m = 0; m < 4; m++) {
        ull zo = zr[2 * m + 1];
#pragma unroll
        for (int i = 0; i < 5; i++) fma2(B[i], pe[i + m], zo);
    }
}

__global__ void __launch_bounds__(256, 2) ncc_k_cross(const float* __restrict__ x,
                                                      float* __restrict__ out) {
    extern __shared__ float sm[];
    float* tile = sm;
    float* zs = sm + TILE_F;                 // plain z floats [512]

    int b = blockIdx.z;
    int d0 = blockIdx.x * 4, h0 = blockIdx.y * 8;
    int tid = threadIdx.x;

    // ---- vectorized prologue: 165 rows x 32 data granules, LDG.128/STS.128
    const float* xb = x + (size_t)b * 2097152;
    for (int i = tid; i < 165 * 32; i += 256) {
        int row = i >> 5;
        int g = i & 31;
        int phys = g ^ (g >> 3);
        int dd = row / CTHH, hh = row - dd * CTHH;
        int gd = min(d0 + dd, 127), gh = min(h0 + hh, 127);
        float4 v = *(const float4*)(xb + ((size_t)(gd * 128 + gh) << 7) + (g << 2));
        *(float4*)(tile + row * RST + (phys << 2)) = v;
    }
    // zero pad granules: logical 32,33 -> phys 36,37
    for (int i = tid; i < 165 * 2; i += 256) {
        int row = i >> 1;
        int phys = 36 + (i & 1);
        *(float4*)(tile + row * RST + (phys << 2)) = make_float4(0.f, 0.f, 0.f, 0.f);
    }
    for (int t = tid; t < 512; t += 256) zs[t] = g_zc[b * 512 + t];
    __syncthreads();

    int wt = tid & 15, c = tid >> 4;
    int od = c >> 2, oh0 = (c & 3) * 2;
    int wb = wt * 8;

    int off[4];
#pragma unroll
    for (int q = 0; q < 4; q++) {
        int g = 2 * wt + q;
        off[q] = (g ^ (g >> 3)) << 2;        // swizzled float offset
    }

    ull A0[4], B0[5], A1[4], B1[5];
#pragma unroll
    for (int p = 0; p < 4; p++) { A0[p] = 0ull; A1[p] = 0ull; }
#pragma unroll
    for (int i = 0; i < 5; i++) { B0[i] = 0ull; B1[i] = 0ull; }

#pragma unroll 1
    for (int kd = 0; kd < 8; kd++) {
        const float* bp = tile + (od + kd) * (CTHH * RST) + oh0 * RST;
        const float* zk = zs + (kd << 6);    // 64 plain z floats for this kd

        ull peb[2][8];
        cr_loadrow(peb[0], bp, off);

        float zcb[2][16];                    // double-buffered z chunks
        cr_loadz(zcb[0], zk);

#pragma unroll
        for (int rh = 0; rh < 4; rh++) {
            if (rh < 3) cr_loadz(zcb[(rh + 1) & 1], zk + ((rh + 1) << 4));
            const float* zc = zcb[rh & 1];
#pragma unroll
            for (int rr = 0; rr < 2; rr++) {
                int r = rh * 2 + rr;
                ull zd[8];
#pragma unroll
                for (int j = 0; j < 8; j++) zd[j] = dupf(zc[rr * 8 + j]);
                cr_loadrow(peb[(r + 1) & 1], bp + (r + 1) * RST, off);
                // phase0: output row oh0,   tile row r,   z row r
                cr_fma(A0, B0, peb[r & 1], zd);
                // phase1: output row oh0+1, tile row r+1, z row r
                cr_fma(A1, B1, peb[(r + 1) & 1], zd);
            }
        }
    }

    int d = d0 + od;
    if (d >= 121) return;
    size_t dbase_o = ((size_t)(b * 121 + d)) * 121;

    {
        int h = h0 + oh0;
        if (h < 121) {
            float res[8];
#pragma unroll
            for (int p = 0; p < 4; p++) {
                float2 a = u2f(A0[p]);
                float2 bl = u2f(B0[p]);
                float2 br = u2f(B0[p + 1]);
                res[2 * p] = a.x + bl.y;
                res[2 * p + 1] = a.y + br.x;
            }
            size_t base = (dbase_o + h) * 121;
#pragma unroll
            for (int j = 0; j < 8; j++) {
                int w = wb + j;
                if (w < 121) out[base + w] = res[j] * __ldg(&g_dinv[base + w]);
            }
        }
    }
    {
        int h = h0 + oh0 + 1;
        if (h < 121) {
            float res[8];
#pragma unroll
            for (int p = 0; p < 4; p++) {
                float2 a = u2f(A1[p]);
                float2 bl = u2f(B1[p]);
                float2 br = u2f(B1[p + 1]);
                res[2 * p] = a.x + bl.y;
                res[2 * p + 1] = a.y + br.x;
            }
            size_t base = (dbase_o + h) * 121;
#pragma unroll
            for (int j = 0; j < 8; j++) {
                int w = wb + j;
                if (w < 121) out[base + w] = res[j] * __ldg(&g_dinv[base + w]);
            }
        }
    }
}

// ---------------------------------------------------------------------------
extern "C" void kernel_launch(void* const* d_in, const int* in_sizes, int n_in,
                              void* d_out, int out_size) {
    (void)n_in;
    (void)out_size;
    const float* z = (const float*)d_in[0];
    const float* x = (const float*)d_in[1];
    if (in_sizes[0] != NB * 512) {
        z = (const float*)d_in[1];
        x = (const float*)d_in[0];
    }
    float* out = (float*)d_out;

    cudaFuncSetAttribute(ncc_k_whsum2,
                         cudaFuncAttributeMaxDynamicSharedMemorySize, WH2_SMEM);
    cudaFuncSetAttribute(ncc_k_cross,
                         cudaFuncAttributeMaxDynamicSharedMemorySize, CR_SMEM);

    ncc_k_template<<<NB, 512>>>(z);
    ncc_k_whsum2<<<dim3(2, NB * 128), 256, WH2_SMEM>>>(x);
    ncc_k_dsum2<<<dim3(58, 4, NB), 256>>>();
    ncc_k_cross<<<dim3(31, 16, NB), 256, CR_SMEM>>>(x, out);
}